// round 13
// baseline (speedup 1.0000x reference)
#include <cuda_runtime.h>
#include <cuda_fp16.h>
#include <cstdint>

#define N_NODES 40000
#define N_EDGES 640000
#define D_FEAT  128

#define NB          500                      // dst buckets
#define NPB         80                       // nodes per bucket (40000/500)
#define HIST_BLOCKS 250
#define EPB_HIST    (N_EDGES / HIST_BLOCKS)  // 2560 edges per hist block
#define SCAT_BLOCKS 250
#define EPB_SCAT    (N_EDGES / SCAT_BLOCKS)  // 2560 edges per scatter block

// ---------------------------------------------------------------------------
// Scratch (allocation-free __device__ globals; zero-initialized at load)
// ---------------------------------------------------------------------------
__device__ __align__(256) uint4 g_fh4[N_NODES * D_FEAT / 8]; // fp16 feats (10.2 MB)
__device__ unsigned long long   g_pk[N_EDGES];   // packed (eid<<24 | dl<<17 | src), dst-bucketed
__device__ float                g_ee[N_EDGES];   // exp(e), bucketed order
__device__ int                  g_count[NB];     // bucket histogram (re-zeroed by scan each replay)
__device__ int                  g_base[NB + 1];  // bucket offsets
__device__ int                  g_cursor[NB];    // scatter reservation cursors

// ---------------------------------------------------------------------------
// 256-bit load/store helpers (sm_100+)
// ---------------------------------------------------------------------------
__device__ __forceinline__ void ldg256(const void* p, uint32_t* r) {
    asm volatile("ld.global.nc.v8.b32 {%0,%1,%2,%3,%4,%5,%6,%7}, [%8];"
                 : "=r"(r[0]), "=r"(r[1]), "=r"(r[2]), "=r"(r[3]),
                   "=r"(r[4]), "=r"(r[5]), "=r"(r[6]), "=r"(r[7])
                 : "l"(p));
}
__device__ __forceinline__ void stg256(void* p, const uint32_t* r) {
    asm volatile("st.global.v8.b32 [%0], {%1,%2,%3,%4,%5,%6,%7,%8};"
                 :: "l"(p),
                    "r"(r[0]), "r"(r[1]), "r"(r[2]), "r"(r[3]),
                    "r"(r[4]), "r"(r[5]), "r"(r[6]), "r"(r[7])
                 : "memory");
}

// |a-b|_1 over 32 B: a8[0..3] vs x, a8[4..7] vs y (fp16 pairs, fp32 accumulate)
__device__ __forceinline__ float l1_32B(const uint32_t* a8, uint4 x, uint4 y) {
    const uint32_t* bx = (const uint32_t*)&x;
    const uint32_t* by = (const uint32_t*)&y;
    float acc = 0.0f;
#pragma unroll
    for (int j = 0; j < 4; j++) {
        __half2 d0 = __habs2(__hsub2(*(const __half2*)&a8[j],     *(const __half2*)&bx[j]));
        __half2 d1 = __habs2(__hsub2(*(const __half2*)&a8[4 + j], *(const __half2*)&by[j]));
        float2 f0 = __half22float2(d0);
        float2 f1 = __half22float2(d1);
        acc += (f0.x + f0.y) + (f1.x + f1.y);
    }
    return acc;
}

// ---------------------------------------------------------------------------
// K1: convert feats fp32->fp16 (16 floats/thread); blocks 0..249 also build
// the dst-bucket histogram (smem-aggregated, then one atomic per bucket).
// g_count is 0 at entry: zero-init at load, re-zeroed by K2 each replay.
// ---------------------------------------------------------------------------
__global__ __launch_bounds__(256) void convert_hist_kernel(const float* __restrict__ feats,
                                                           const int* __restrict__ dst) {
    __shared__ int h[NB];
    int i = blockIdx.x * 256 + threadIdx.x;              // [0, 320000)

    uint32_t v[16];
    ldg256(feats + (size_t)i * 16,     v);
    ldg256(feats + (size_t)i * 16 + 8, v + 8);
    uint32_t hh[8];
    const float* f = (const float*)v;
#pragma unroll
    for (int j = 0; j < 8; j++) {
        __half2 h2 = __floats2half2_rn(f[2 * j], f[2 * j + 1]);
        hh[j] = *(const uint32_t*)&h2;
    }
    stg256((char*)g_fh4 + (size_t)i * 32, hh);

    if (blockIdx.x < HIST_BLOCKS) {
        for (int b = threadIdx.x; b < NB; b += 256) h[b] = 0;
        __syncthreads();
        int e0 = blockIdx.x * EPB_HIST;
        for (int k = threadIdx.x; k < EPB_HIST; k += 256)
            atomicAdd(&h[dst[e0 + k] / NPB], 1);
        __syncthreads();
        for (int b = threadIdx.x; b < NB; b += 256)
            if (h[b]) atomicAdd(&g_count[b], h[b]);
    }
}

// ---------------------------------------------------------------------------
// K2: single-block scan of g_count -> g_base / g_cursor; re-zeroes g_count
// for the next replay (graph-capture safe: every call sees count==0 at K1).
// ---------------------------------------------------------------------------
__global__ __launch_bounds__(512) void scan_kernel() {
    __shared__ int sm[512];
    int t = threadIdx.x;
    int c = (t < NB) ? g_count[t] : 0;
    sm[t] = c;
    __syncthreads();
    for (int d = 1; d < 512; d <<= 1) {
        int v = (t >= d) ? sm[t - d] : 0;
        __syncthreads();
        sm[t] += v;
        __syncthreads();
    }
    int excl = sm[t] - c;                                // exclusive prefix
    if (t < NB) {
        g_base[t]   = excl;
        g_cursor[t] = excl;
        g_count[t]  = 0;                                 // reset for next replay
    }
    if (t == 511) g_base[NB] = sm[511];                  // total == N_EDGES
}

// ---------------------------------------------------------------------------
// K3: scatter edges into bucket-contiguous order as packed u64
// (eid:20 | dst_local:7 | src:17). Block-staged: smem hist -> one global
// reservation per (block,bucket) -> smem slot cursors -> 8B writes.
// ---------------------------------------------------------------------------
__global__ __launch_bounds__(256) void scatter_kernel(const int* __restrict__ src,
                                                      const int* __restrict__ dst) {
    __shared__ int h[NB];
    __shared__ int slot[NB];
    int t = threadIdx.x;
    int e0 = blockIdx.x * EPB_SCAT;

    for (int b = t; b < NB; b += 256) h[b] = 0;
    __syncthreads();
    for (int k = t; k < EPB_SCAT; k += 256)
        atomicAdd(&h[dst[e0 + k] / NPB], 1);
    __syncthreads();
    for (int b = t; b < NB; b += 256)
        slot[b] = h[b] ? atomicAdd(&g_cursor[b], h[b]) : 0;
    __syncthreads();
    for (int k = t; k < EPB_SCAT; k += 256) {
        int e  = e0 + k;
        int d  = dst[e];
        int b  = d / NPB;
        int dl = d - b * NPB;
        int p  = atomicAdd(&slot[b], 1);
        g_pk[p] = ((unsigned long long)(unsigned)e << 24) |
                  ((unsigned long long)(unsigned)dl << 17) |
                  (unsigned long long)(unsigned)src[e];
    }
}

// ---------------------------------------------------------------------------
// K4: one block per bucket. dst rows cached in smem (80 x 256B = 20KB), sums
// in smem u64 fixed-point (deterministic), finalize fused.
// 4 lanes per edge: 2 front-batched LDG.256 for the src row; dst from smem.
//   ee = exp(exp(-0.01 * L1))   (segment-max pass mathematically unnecessary)
// ---------------------------------------------------------------------------
__global__ __launch_bounds__(512) void bucket_kernel(float* __restrict__ out) {
    __shared__ __align__(16) uint4 rows[NPB * 16];       // 20 KB
    __shared__ unsigned long long  sums[NPB];

    int b = blockIdx.x;
    int t = threadIdx.x;

    for (int i = t; i < NPB * 16; i += 512) rows[i] = g_fh4[b * NPB * 16 + i];
    for (int i = t; i < NPB; i += 512) sums[i] = 0ULL;
    int beg = g_base[b];
    int end = g_base[b + 1];
    __syncthreads();

    int lane = t & 3, grp = t >> 2;                      // 128 groups of 4 lanes
    int cnt  = end - beg;
    int kmax = (cnt + 127) / 128;                        // uniform per block

    for (int k = 0; k < kmax; k++) {
        int idx   = beg + grp + k * 128;
        bool valid = idx < end;
        int ridx  = valid ? idx : beg;

        unsigned long long pk = g_pk[ridx];              // 4-lane broadcast
        int s  = (int)(pk & 0x1FFFF);
        int dl = (int)((pk >> 17) & 0x7F);

        const char* base2 = (const char*)g_fh4;
        uint32_t a0[8], a1[8];
        ldg256(base2 + (size_t)s * 256 +       lane * 32, a0);
        ldg256(base2 + (size_t)s * 256 + 128 + lane * 32, a1);

        const uint4* r = &rows[dl * 16];
        uint4 b0a = r[lane * 2], b0b = r[lane * 2 + 1];
        uint4 b1a = r[8 + lane * 2], b1b = r[8 + lane * 2 + 1];

        float acc = l1_32B(a0, b0a, b0b) + l1_32B(a1, b1a, b1b);

        acc += __shfl_xor_sync(0xffffffffu, acc, 2);
        acc += __shfl_xor_sync(0xffffffffu, acc, 1);

        if (lane == 0 && valid) {
            float ee = __expf(__expf(-0.01f * acc));
            g_ee[idx] = ee;
            atomicAdd(&sums[dl], (unsigned long long)(ee * 4294967296.0f));
        }
    }
    __syncthreads();

    // fused finalize: out[eid] = ee / sum[dst]
    for (int i = beg + t; i < end; i += 512) {
        unsigned long long pk = g_pk[i];
        int dl  = (int)((pk >> 17) & 0x7F);
        int eid = (int)(pk >> 24);
        out[eid] = __fdividef(g_ee[i], (float)sums[dl] * 0x1p-32f);
    }
}

// ---------------------------------------------------------------------------
extern "C" void kernel_launch(void* const* d_in, const int* in_sizes, int n_in,
                              void* d_out, int out_size) {
    const float* feats = (const float*)d_in[0];
    const int*   src   = (const int*)d_in[1];
    const int*   dst   = (const int*)d_in[2];
    float*       out   = (float*)d_out;

    convert_hist_kernel<<<N_NODES * D_FEAT / 16 / 256, 256>>>(feats, dst);
    scan_kernel<<<1, 512>>>();
    scatter_kernel<<<SCAT_BLOCKS, 256>>>(src, dst);
    bucket_kernel<<<NB, 512>>>(out);
}

// round 14
// speedup vs baseline: 1.8949x; 1.8949x over previous
#include <cuda_runtime.h>
#include <cuda_fp16.h>
#include <cstdint>

#define N_NODES 40000
#define N_EDGES 640000
#define D_FEAT  128

// ---------------------------------------------------------------------------
// Scratch (allocation-free: __device__ globals)
// g_fh4 aligned 256 B so 32 B (v8.b32) accesses are always aligned.
// ---------------------------------------------------------------------------
__device__ __align__(256) uint4 g_fh4[N_NODES * D_FEAT / 8]; // fp16 feats (10.2 MB)
__device__ float              g_ee[N_EDGES];                 // exp(e) per edge
__device__ unsigned long long g_sum[N_NODES];                // fixed-point 2^32 sums

// ---------------------------------------------------------------------------
// 256-bit load/store helpers (sm_100+: .v8.b32)
// ---------------------------------------------------------------------------
__device__ __forceinline__ void ldg256(const void* p, uint32_t* r) {
    asm volatile("ld.global.nc.v8.b32 {%0,%1,%2,%3,%4,%5,%6,%7}, [%8];"
                 : "=r"(r[0]), "=r"(r[1]), "=r"(r[2]), "=r"(r[3]),
                   "=r"(r[4]), "=r"(r[5]), "=r"(r[6]), "=r"(r[7])
                 : "l"(p));
}
__device__ __forceinline__ void stg256(void* p, const uint32_t* r) {
    asm volatile("st.global.v8.b32 [%0], {%1,%2,%3,%4,%5,%6,%7,%8};"
                 :: "l"(p),
                    "r"(r[0]), "r"(r[1]), "r"(r[2]), "r"(r[3]),
                    "r"(r[4]), "r"(r[5]), "r"(r[6]), "r"(r[7])
                 : "memory");
}

// L1 distance over one 32 B chunk pair (16 fp16 lanes), fp32 accumulate
__device__ __forceinline__ float l1_chunk(const uint32_t* a, const uint32_t* b) {
    float acc = 0.0f;
#pragma unroll
    for (int j = 0; j < 8; j++) {
        __half2 d = __habs2(__hsub2(*(const __half2*)&a[j], *(const __half2*)&b[j]));
        float2 f = __half22float2(d);
        acc += f.x + f.y;
    }
    return acc;
}

// ---------------------------------------------------------------------------
// K1: convert feats fp32 -> fp16 + zero g_sum.
// Thread i handles 16 consecutive floats: 2 x LDG.256 -> 1 x STG.256.
// (DRAM-read bound in cold runs; L2-resident in steady state.)
// ---------------------------------------------------------------------------
__global__ __launch_bounds__(256) void convert_kernel(const float* __restrict__ feats) {
    int i = blockIdx.x * blockDim.x + threadIdx.x;     // [0, 320000)

    uint32_t v[16];
    ldg256(feats + (size_t)i * 16,     v);
    ldg256(feats + (size_t)i * 16 + 8, v + 8);

    uint32_t h[8];
    const float* f = (const float*)v;
#pragma unroll
    for (int j = 0; j < 8; j++) {
        __half2 hh = __floats2half2_rn(f[2 * j], f[2 * j + 1]);
        h[j] = *(const uint32_t*)&hh;
    }
    stg256((char*)g_fh4 + (size_t)i * 32, h);

    if (i < N_NODES) g_sum[i] = 0ULL;
}

// ---------------------------------------------------------------------------
// K2: 2 lanes per edge (16 edges/warp).
// Row = 256 B. Lane l covers 128 B of each row as 4 x 32 B chunks at offsets
// l*32 + j*64 (adjacent lanes read adjacent chunks -> 100% sector efficiency).
// 8 independent front-batched LDG.256 per thread (MLP_p1 = 8).
//   e  = exp(-0.01 * L1)  in (0, 1]
//   ee = exp(e)           in (1, 2.72]   (segment-max pass mathematically moot)
// Leader lane stores ee and adds fixed-point ee to g_sum[dst]
// (u64 integer atomics are associative -> deterministic).
// ---------------------------------------------------------------------------
__global__ __launch_bounds__(256) void edge_kernel(const int* __restrict__ src,
                                                   const int* __restrict__ dst) {
    int t    = blockIdx.x * blockDim.x + threadIdx.x;
    int edge = t >> 1;
    int lane = t & 1;
    if (edge >= N_EDGES) return;

    int s = src[edge];                     // broadcast within 2-group
    int d = dst[edge];

    const char* sb = (const char*)g_fh4 + (size_t)s * 256 + lane * 32;
    const char* db = (const char*)g_fh4 + (size_t)d * 256 + lane * 32;

    uint32_t a[4][8], b[4][8];
#pragma unroll
    for (int j = 0; j < 4; j++) ldg256(sb + j * 64, a[j]);
#pragma unroll
    for (int j = 0; j < 4; j++) ldg256(db + j * 64, b[j]);

    float acc = 0.0f;
#pragma unroll
    for (int j = 0; j < 4; j++) acc += l1_chunk(a[j], b[j]);

    acc += __shfl_xor_sync(0xffffffffu, acc, 1);

    if (lane == 0) {
        float e  = __expf(-0.01f * acc);
        float ee = __expf(e);
        g_ee[edge] = ee;
        unsigned long long q = (unsigned long long)(ee * 4294967296.0f);
        atomicAdd(&g_sum[d], q);
    }
}

// ---------------------------------------------------------------------------
// K3: out[i] = ee[i] / sum[dst[i]], 4 edges per thread (vectorized).
// ---------------------------------------------------------------------------
__global__ __launch_bounds__(256) void finalize_kernel(const int4* __restrict__ dst4,
                                                       float4* __restrict__ out4) {
    int i = blockIdx.x * blockDim.x + threadIdx.x;     // [0, 160000)
    if (i < N_EDGES / 4) {
        int4   d = dst4[i];
        float4 e = ((const float4*)g_ee)[i];
        float4 r;
        r.x = __fdividef(e.x, (float)g_sum[d.x] * 0x1p-32f);
        r.y = __fdividef(e.y, (float)g_sum[d.y] * 0x1p-32f);
        r.z = __fdividef(e.z, (float)g_sum[d.z] * 0x1p-32f);
        r.w = __fdividef(e.w, (float)g_sum[d.w] * 0x1p-32f);
        out4[i] = r;
    }
}

// ---------------------------------------------------------------------------
extern "C" void kernel_launch(void* const* d_in, const int* in_sizes, int n_in,
                              void* d_out, int out_size) {
    const float* feats = (const float*)d_in[0];
    const int*   src   = (const int*)d_in[1];
    const int*   dst   = (const int*)d_in[2];
    float*       out   = (float*)d_out;

    // 320000 threads, each converts 16 floats
    convert_kernel<<<(N_NODES * D_FEAT / 16) / 256, 256>>>(feats);

    // 2 lanes per edge: 640000 * 2 = 1.28M threads
    edge_kernel<<<(N_EDGES * 2) / 256, 256>>>(src, dst);

    finalize_kernel<<<(N_EDGES / 4 + 255) / 256, 256>>>((const int4*)dst,
                                                        (float4*)out);
}

// round 15
// speedup vs baseline: 2.3455x; 1.2378x over previous
#include <cuda_runtime.h>
#include <cuda_fp16.h>
#include <cstdint>

#define N_NODES 40000
#define N_EDGES 640000
#define D_FEAT  128
#define HALF_E  (N_EDGES / 2)

// ---------------------------------------------------------------------------
// Scratch (allocation-free: __device__ globals)
// g_fh4 aligned 256 B so 32 B (v8.b32) accesses are always aligned.
// ---------------------------------------------------------------------------
__device__ __align__(256) uint4 g_fh4[N_NODES * D_FEAT / 8]; // fp16 feats (10.2 MB)
__device__ float              g_ee[N_EDGES];                 // exp(e) per edge
__device__ unsigned long long g_sum[N_NODES];                // fixed-point 2^32 sums

// ---------------------------------------------------------------------------
// 256-bit load/store helpers (sm_100+: .v8.b32)
// ---------------------------------------------------------------------------
__device__ __forceinline__ void ldg256(const void* p, uint32_t* r) {
    asm volatile("ld.global.nc.v8.b32 {%0,%1,%2,%3,%4,%5,%6,%7}, [%8];"
                 : "=r"(r[0]), "=r"(r[1]), "=r"(r[2]), "=r"(r[3]),
                   "=r"(r[4]), "=r"(r[5]), "=r"(r[6]), "=r"(r[7])
                 : "l"(p));
}
__device__ __forceinline__ void stg256(void* p, const uint32_t* r) {
    asm volatile("st.global.v8.b32 [%0], {%1,%2,%3,%4,%5,%6,%7,%8};"
                 :: "l"(p),
                    "r"(r[0]), "r"(r[1]), "r"(r[2]), "r"(r[3]),
                    "r"(r[4]), "r"(r[5]), "r"(r[6]), "r"(r[7])
                 : "memory");
}

// L1 distance over one 32 B chunk pair (16 fp16 lanes), fp32 accumulate
__device__ __forceinline__ float l1_chunk(const uint32_t* a, const uint32_t* b) {
    float acc = 0.0f;
#pragma unroll
    for (int j = 0; j < 8; j++) {
        __half2 d = __habs2(__hsub2(*(const __half2*)&a[j], *(const __half2*)&b[j]));
        float2 f = __half22float2(d);
        acc += f.x + f.y;
    }
    return acc;
}

// ---------------------------------------------------------------------------
// K1: convert feats fp32 -> fp16 + zero g_sum.
// Thread i handles 16 consecutive floats: 2 x LDG.256 -> 1 x STG.256.
// ---------------------------------------------------------------------------
__global__ __launch_bounds__(256) void convert_kernel(const float* __restrict__ feats) {
    int i = blockIdx.x * blockDim.x + threadIdx.x;     // [0, 320000)

    uint32_t v[16];
    ldg256(feats + (size_t)i * 16,     v);
    ldg256(feats + (size_t)i * 16 + 8, v + 8);

    uint32_t h[8];
    const float* f = (const float*)v;
#pragma unroll
    for (int j = 0; j < 8; j++) {
        __half2 hh = __floats2half2_rn(f[2 * j], f[2 * j + 1]);
        h[j] = *(const uint32_t*)&hh;
    }
    stg256((char*)g_fh4 + (size_t)i * 32, h);

    if (i < N_NODES) g_sum[i] = 0ULL;
}

// ---------------------------------------------------------------------------
// K2: 4 lanes per edge-group; each group processes TWO independent edges
// (e0 and e0 + HALF_E). All 8 LDG.256 front-batched (MLP_p1 = 8), while each
// instruction keeps the proven 8-rows x 128 B warp pattern (8 segments/inst —
// R14 showed 16 segments/inst regresses).
//   e  = exp(-0.01 * L1)  in (0, 1]
//   ee = exp(e)           in (1, 2.72]   (segment-max pass mathematically moot)
// Leader lane stores ee and adds fixed-point ee to g_sum[dst]
// (u64 integer atomics are associative -> deterministic).
// ---------------------------------------------------------------------------
__global__ __launch_bounds__(256) void edge_kernel(const int* __restrict__ src,
                                                   const int* __restrict__ dst) {
    int t    = blockIdx.x * blockDim.x + threadIdx.x;
    int e0   = t >> 2;                    // [0, HALF_E)
    int lane = t & 3;
    if (e0 >= HALF_E) return;
    int e1 = e0 + HALF_E;

    int s0 = src[e0], d0 = dst[e0];       // broadcast within 4-group
    int s1 = src[e1], d1 = dst[e1];

    const char* base = (const char*)g_fh4;
    uint32_t a0[8], a1[8], b0[8], b1[8];  // edge 0
    uint32_t c0[8], c1[8], f0[8], f1[8];  // edge 1
    ldg256(base + (size_t)s0 * 256 +       lane * 32, a0);
    ldg256(base + (size_t)s0 * 256 + 128 + lane * 32, a1);
    ldg256(base + (size_t)d0 * 256 +       lane * 32, b0);
    ldg256(base + (size_t)d0 * 256 + 128 + lane * 32, b1);
    ldg256(base + (size_t)s1 * 256 +       lane * 32, c0);
    ldg256(base + (size_t)s1 * 256 + 128 + lane * 32, c1);
    ldg256(base + (size_t)d1 * 256 +       lane * 32, f0);
    ldg256(base + (size_t)d1 * 256 + 128 + lane * 32, f1);

    float accA = l1_chunk(a0, b0) + l1_chunk(a1, b1);
    float accB = l1_chunk(c0, f0) + l1_chunk(c1, f1);

    accA += __shfl_xor_sync(0xffffffffu, accA, 2);
    accA += __shfl_xor_sync(0xffffffffu, accA, 1);
    accB += __shfl_xor_sync(0xffffffffu, accB, 2);
    accB += __shfl_xor_sync(0xffffffffu, accB, 1);

    if (lane == 0) {
        float eeA = __expf(__expf(-0.01f * accA));
        g_ee[e0] = eeA;
        atomicAdd(&g_sum[d0], (unsigned long long)(eeA * 4294967296.0f));
    } else if (lane == 1) {
        float eeB = __expf(__expf(-0.01f * accB));
        g_ee[e1] = eeB;
        atomicAdd(&g_sum[d1], (unsigned long long)(eeB * 4294967296.0f));
    }
}

// ---------------------------------------------------------------------------
// K3: out[i] = ee[i] / sum[dst[i]], 4 edges per thread (vectorized).
// ---------------------------------------------------------------------------
__global__ __launch_bounds__(256) void finalize_kernel(const int4* __restrict__ dst4,
                                                       float4* __restrict__ out4) {
    int i = blockIdx.x * blockDim.x + threadIdx.x;     // [0, 160000)
    if (i < N_EDGES / 4) {
        int4   d = dst4[i];
        float4 e = ((const float4*)g_ee)[i];
        float4 r;
        r.x = __fdividef(e.x, (float)g_sum[d.x] * 0x1p-32f);
        r.y = __fdividef(e.y, (float)g_sum[d.y] * 0x1p-32f);
        r.z = __fdividef(e.z, (float)g_sum[d.z] * 0x1p-32f);
        r.w = __fdividef(e.w, (float)g_sum[d.w] * 0x1p-32f);
        out4[i] = r;
    }
}

// ---------------------------------------------------------------------------
extern "C" void kernel_launch(void* const* d_in, const int* in_sizes, int n_in,
                              void* d_out, int out_size) {
    const float* feats = (const float*)d_in[0];
    const int*   src   = (const int*)d_in[1];
    const int*   dst   = (const int*)d_in[2];
    float*       out   = (float*)d_out;

    // 320000 threads, each converts 16 floats
    convert_kernel<<<(N_NODES * D_FEAT / 16) / 256, 256>>>(feats);

    // 4 lanes per 2-edge group: 320000 groups * 4 = 1.28M threads
    edge_kernel<<<(HALF_E * 4) / 256, 256>>>(src, dst);

    finalize_kernel<<<(N_EDGES / 4 + 255) / 256, 256>>>((const int4*)dst,
                                                        (float4*)out);
}

// round 16
// speedup vs baseline: 2.3648x; 1.0082x over previous
#include <cuda_runtime.h>
#include <cuda_fp16.h>
#include <cstdint>

#define N_NODES 40000
#define N_EDGES 640000
#define D_FEAT  128

// ---------------------------------------------------------------------------
// Scratch (allocation-free: __device__ globals)
// g_fh4 aligned 256 B so 32 B (v8.b32) accesses are always aligned.
// ---------------------------------------------------------------------------
__device__ __align__(256) uint4 g_fh4[N_NODES * D_FEAT / 8]; // fp16 feats (10.2 MB)
__device__ float              g_ee[N_EDGES];                 // exp(e) per edge
__device__ unsigned long long g_sum[N_NODES];                // fixed-point 2^32 sums

// ---------------------------------------------------------------------------
// 256-bit load/store helpers (sm_100+: .v8.b32)
// ---------------------------------------------------------------------------
__device__ __forceinline__ void ldg256(const void* p, uint32_t* r) {
    asm volatile("ld.global.nc.v8.b32 {%0,%1,%2,%3,%4,%5,%6,%7}, [%8];"
                 : "=r"(r[0]), "=r"(r[1]), "=r"(r[2]), "=r"(r[3]),
                   "=r"(r[4]), "=r"(r[5]), "=r"(r[6]), "=r"(r[7])
                 : "l"(p));
}
__device__ __forceinline__ void stg256(void* p, const uint32_t* r) {
    asm volatile("st.global.v8.b32 [%0], {%1,%2,%3,%4,%5,%6,%7,%8};"
                 :: "l"(p),
                    "r"(r[0]), "r"(r[1]), "r"(r[2]), "r"(r[3]),
                    "r"(r[4]), "r"(r[5]), "r"(r[6]), "r"(r[7])
                 : "memory");
}

// L1 distance over one 32 B chunk pair (16 fp16 lanes), fp32 accumulate
__device__ __forceinline__ float l1_chunk(const uint32_t* a, const uint32_t* b) {
    float acc = 0.0f;
#pragma unroll
    for (int j = 0; j < 8; j++) {
        __half2 d = __habs2(__hsub2(*(const __half2*)&a[j], *(const __half2*)&b[j]));
        float2 f = __half22float2(d);
        acc += f.x + f.y;
    }
    return acc;
}

// ---------------------------------------------------------------------------
// K1: convert feats fp32 -> fp16 + zero g_sum.
// Thread i handles 16 consecutive floats: 2 x LDG.256 -> 1 x STG.256.
// ---------------------------------------------------------------------------
__global__ __launch_bounds__(256) void convert_kernel(const float* __restrict__ feats) {
    int i = blockIdx.x * blockDim.x + threadIdx.x;     // [0, 320000)

    uint32_t v[16];
    ldg256(feats + (size_t)i * 16,     v);
    ldg256(feats + (size_t)i * 16 + 8, v + 8);

    uint32_t h[8];
    const float* f = (const float*)v;
#pragma unroll
    for (int j = 0; j < 8; j++) {
        __half2 hh = __floats2half2_rn(f[2 * j], f[2 * j + 1]);
        h[j] = *(const uint32_t*)&hh;
    }
    stg256((char*)g_fh4 + (size_t)i * 32, h);

    if (i < N_NODES) g_sum[i] = 0ULL;

    cudaTriggerProgrammaticLaunchCompletion();
}

// ---------------------------------------------------------------------------
// K2: 4 lanes per edge (8 edges/warp), PDL secondary of convert.
// Prologue (src/dst index loads) is independent of convert output and runs
// while convert drains; cudaGridDependencySynchronize() gates g_fh4 reads.
// Row = 256 B. Lane l loads 32 B chunks l and l+4 of both rows:
// 4 front-batched LDG.256 per thread, 8-rows x 128 B per instruction
// (proven best warp pattern; R14 showed 16-segment instructions regress).
//   e  = exp(-0.01 * L1)  in (0, 1]
//   ee = exp(e)           in (1, 2.72]   (segment-max pass mathematically moot)
// Leader lane stores ee and adds fixed-point ee to g_sum[dst]
// (u64 integer atomics are associative -> deterministic).
// ---------------------------------------------------------------------------
__global__ __launch_bounds__(256) void edge_kernel(const int* __restrict__ src,
                                                   const int* __restrict__ dst) {
    int t    = blockIdx.x * blockDim.x + threadIdx.x;
    int edge = t >> 2;
    int lane = t & 3;

    int s = src[edge];                    // independent of convert output
    int d = dst[edge];

    cudaGridDependencySynchronize();      // wait for convert's g_fh4/g_sum

    const char* base = (const char*)g_fh4;
    uint32_t a0[8], a1[8], b0[8], b1[8];
    ldg256(base + (size_t)s * 256 +       lane * 32, a0);
    ldg256(base + (size_t)s * 256 + 128 + lane * 32, a1);
    ldg256(base + (size_t)d * 256 +       lane * 32, b0);
    ldg256(base + (size_t)d * 256 + 128 + lane * 32, b1);

    float acc = l1_chunk(a0, b0) + l1_chunk(a1, b1);

    acc += __shfl_xor_sync(0xffffffffu, acc, 2);
    acc += __shfl_xor_sync(0xffffffffu, acc, 1);

    if (lane == 0) {
        float e  = __expf(-0.01f * acc);
        float ee = __expf(e);
        g_ee[edge] = ee;
        unsigned long long q = (unsigned long long)(ee * 4294967296.0f);
        atomicAdd(&g_sum[d], q);
    }

    cudaTriggerProgrammaticLaunchCompletion();
}

// ---------------------------------------------------------------------------
// K3: out[i] = ee[i] / sum[dst[i]], 4 edges/thread. PDL secondary of edge:
// dst4 loads run during edge drain; sync gates g_ee/g_sum reads.
// ---------------------------------------------------------------------------
__global__ __launch_bounds__(256) void finalize_kernel(const int4* __restrict__ dst4,
                                                       float4* __restrict__ out4) {
    int i = blockIdx.x * blockDim.x + threadIdx.x;     // [0, 160000)

    int4 d = dst4[i];                     // independent of edge output

    cudaGridDependencySynchronize();      // wait for edge's g_ee/g_sum

    float4 e = ((const float4*)g_ee)[i];
    float4 r;
    r.x = __fdividef(e.x, (float)g_sum[d.x] * 0x1p-32f);
    r.y = __fdividef(e.y, (float)g_sum[d.y] * 0x1p-32f);
    r.z = __fdividef(e.z, (float)g_sum[d.z] * 0x1p-32f);
    r.w = __fdividef(e.w, (float)g_sum[d.w] * 0x1p-32f);
    out4[i] = r;
}

// ---------------------------------------------------------------------------
extern "C" void kernel_launch(void* const* d_in, const int* in_sizes, int n_in,
                              void* d_out, int out_size) {
    const float* feats = (const float*)d_in[0];
    const int*   src   = (const int*)d_in[1];
    const int*   dst   = (const int*)d_in[2];
    float*       out   = (float*)d_out;

    // K1: plain launch (default stream)
    convert_kernel<<<(N_NODES * D_FEAT / 16) / 256, 256>>>(feats);

    cudaLaunchAttribute attr[1];
    attr[0].id = cudaLaunchAttributeProgrammaticStreamSerialization;
    attr[0].val.programmaticStreamSerializationAllowed = 1;

    // K2: PDL secondary of K1
    {
        cudaLaunchConfig_t cfg = {};
        cfg.gridDim  = dim3((N_EDGES * 4) / 256);
        cfg.blockDim = dim3(256);
        cfg.stream   = 0;
        cfg.attrs    = attr;
        cfg.numAttrs = 1;
        cudaLaunchKernelEx(&cfg, edge_kernel, src, dst);
    }

    // K3: PDL secondary of K2
    {
        cudaLaunchConfig_t cfg = {};
        cfg.gridDim  = dim3((N_EDGES / 4) / 256);
        cfg.blockDim = dim3(256);
        cfg.stream   = 0;
        cfg.attrs    = attr;
        cfg.numAttrs = 1;
        cudaLaunchKernelEx(&cfg, finalize_kernel, (const int4*)dst, (float4*)out);
    }
}